// round 2
// baseline (speedup 1.0000x reference)
#include <cuda_runtime.h>
#include <cuda_fp16.h>
#include <mma.h>

using namespace nvcuda;

// ---------------------------------------------------------------------------
// Problem: y[b,s,o] = sum_i x[b,s,i] * w[o,i] + bias[o]
//   w[o, nb*32+j] = (q[o,nb,j] - 128) * scales[o,nb]
// Harness promotes jnp.float16 -> float32. So:
//   x [4,1024,4096] f32, q [4096,128,32] i32, scales [4096,128] f32,
//   bias [4096] f32 -> out [4,1024,4096] f32
// GEMM view: A = x [M=4096, K=4096], B = w [N=4096, K] (row-major, used as
// B^T), C [M,N] row-major, fp16 operands / fp32 accumulate.
// ---------------------------------------------------------------------------

#define MAX_O 4096
#define MAX_K 4096
#define MAX_M 4096

// fp16 scratch (static __device__: allocation-guard safe). 32 MB each.
__device__ __half g_w[(size_t)MAX_O * MAX_K];
__device__ __half g_x[(size_t)MAX_M * MAX_K];

// ---------------------------------------------------------------------------
// Kernel 0: convert x f32 -> f16, vectorized (8 elems/thread).
// ---------------------------------------------------------------------------
__global__ void convert_x_kernel(const float* __restrict__ x, size_t n) {
    size_t i = ((size_t)blockIdx.x * blockDim.x + threadIdx.x) * 8;
    if (i >= n) return;
    const float4* xp = reinterpret_cast<const float4*>(x + i);
    float4 a = xp[0], b = xp[1];
    __half h[8];
    h[0] = __float2half(a.x); h[1] = __float2half(a.y);
    h[2] = __float2half(a.z); h[3] = __float2half(a.w);
    h[4] = __float2half(b.x); h[5] = __float2half(b.y);
    h[6] = __float2half(b.z); h[7] = __float2half(b.w);
    *reinterpret_cast<float4*>(&g_x[i]) = *reinterpret_cast<const float4*>(h);
}

// ---------------------------------------------------------------------------
// Kernel 1: dequantize q int32 -> fp16 weights, coalesced (8 elems/thread,
// all 8 within one 32-wide scale block).
// ---------------------------------------------------------------------------
__global__ void dequant_kernel(const int* __restrict__ q,
                               const float* __restrict__ scales,
                               int O, int K) {
    int c = blockIdx.x * blockDim.x + threadIdx.x;     // chunk of 8 elems
    int chunks_per_row = K >> 3;
    if (c >= O * chunks_per_row) return;
    int o  = c / chunks_per_row;
    int k0 = (c - o * chunks_per_row) << 3;            // 8-aligned
    int nb = k0 >> 5;                                  // 32-block index
    float s = scales[o * (K >> 5) + nb];

    const int4* qp = reinterpret_cast<const int4*>(q + (size_t)o * K + k0);
    int4 q0 = qp[0];
    int4 q1 = qp[1];

    __half h[8];
    h[0] = __float2half((float)(q0.x - 128) * s);
    h[1] = __float2half((float)(q0.y - 128) * s);
    h[2] = __float2half((float)(q0.z - 128) * s);
    h[3] = __float2half((float)(q0.w - 128) * s);
    h[4] = __float2half((float)(q1.x - 128) * s);
    h[5] = __float2half((float)(q1.y - 128) * s);
    h[6] = __float2half((float)(q1.z - 128) * s);
    h[7] = __float2half((float)(q1.w - 128) * s);

    *reinterpret_cast<float4*>(&g_w[(size_t)o * K + k0]) =
        *reinterpret_cast<const float4*>(h);
}

// ---------------------------------------------------------------------------
// Kernel 2: wmma fp16 GEMM, C = A @ B^T + bias (f32 out).
// Block tile 128x128, K-tile 64. 8 warps (2x4); warp tile 64x32 = 4x2
// fragments of 16x16x16. fp32 accumulation.
// ---------------------------------------------------------------------------
constexpr int BM = 128, BN = 128, BK = 64;
constexpr int WM = 64, WN = 32;
constexpr int WMITER = WM / 16;   // 4
constexpr int WNITER = WN / 16;   // 2
constexpr int LDS = BK + 8;       // 72: pad vs bank conflicts; mult of 8

__global__ void __launch_bounds__(256)
gemm_wmma_kernel(const float* __restrict__ bias,
                 float* __restrict__ C,          // [M,N] f32
                 int M, int N, int K) {
    __shared__ __half As[BM][LDS];
    __shared__ __half Bs[BN][LDS];
    __shared__ float  stage[8][16 * 16];

    const int bm = blockIdx.y * BM;
    const int bn = blockIdx.x * BN;
    const int tid  = threadIdx.x;
    const int warp = tid >> 5;
    const int lane = tid & 31;
    const int wrow = warp >> 2;     // 0..1
    const int wcol = warp & 3;      // 0..3

    const __half* A  = g_x;         // [M,K] fp16
    const __half* Bw = g_w;         // [N,K] fp16

    wmma::fragment<wmma::accumulator, 16, 16, 16, float> acc[WMITER][WNITER];
#pragma unroll
    for (int mi = 0; mi < WMITER; mi++)
#pragma unroll
        for (int ni = 0; ni < WNITER; ni++)
            wmma::fill_fragment(acc[mi][ni], 0.0f);

    for (int k0 = 0; k0 < K; k0 += BK) {
        // Load A tile 128x64 + B tile 128x64 (4 float4s each per thread)
#pragma unroll
        for (int i = 0; i < 4; i++) {
            int idx = tid + i * 256;            // 0..1023
            int r = idx >> 3;                   // row 0..127
            int c = (idx & 7) << 3;             // col 0..56 step 8
            *reinterpret_cast<float4*>(&As[r][c]) =
                *reinterpret_cast<const float4*>(&A[(size_t)(bm + r) * K + k0 + c]);
        }
#pragma unroll
        for (int i = 0; i < 4; i++) {
            int idx = tid + i * 256;
            int r = idx >> 3;
            int c = (idx & 7) << 3;
            *reinterpret_cast<float4*>(&Bs[r][c]) =
                *reinterpret_cast<const float4*>(&Bw[(size_t)(bn + r) * K + k0 + c]);
        }
        __syncthreads();

#pragma unroll
        for (int kk = 0; kk < BK; kk += 16) {
            wmma::fragment<wmma::matrix_a, 16, 16, 16, __half, wmma::row_major> af[WMITER];
            wmma::fragment<wmma::matrix_b, 16, 16, 16, __half, wmma::col_major> bf[WNITER];
#pragma unroll
            for (int mi = 0; mi < WMITER; mi++)
                wmma::load_matrix_sync(af[mi], &As[wrow * WM + mi * 16][kk], LDS);
#pragma unroll
            for (int ni = 0; ni < WNITER; ni++)
                wmma::load_matrix_sync(bf[ni], &Bs[wcol * WN + ni * 16][kk], LDS);
#pragma unroll
            for (int mi = 0; mi < WMITER; mi++)
#pragma unroll
                for (int ni = 0; ni < WNITER; ni++)
                    wmma::mma_sync(acc[mi][ni], af[mi], bf[ni], acc[mi][ni]);
        }
        __syncthreads();
    }

    // Epilogue: fragment -> smem stage -> +bias -> f32 vector stores
#pragma unroll
    for (int mi = 0; mi < WMITER; mi++) {
#pragma unroll
        for (int ni = 0; ni < WNITER; ni++) {
            float* st = stage[warp];
            wmma::store_matrix_sync(st, acc[mi][ni], 16, wmma::mem_row_major);
            __syncwarp();
            int r  = lane >> 1;              // 0..15
            int cc = (lane & 1) << 3;        // 0 or 8
            int grow = bm + wrow * WM + mi * 16 + r;
            int gcol = bn + wcol * WN + ni * 16 + cc;
            float out4a[4], out4b[4];
#pragma unroll
            for (int e = 0; e < 4; e++)
                out4a[e] = st[r * 16 + cc + e] + bias[gcol + e];
#pragma unroll
            for (int e = 0; e < 4; e++)
                out4b[e] = st[r * 16 + cc + 4 + e] + bias[gcol + 4 + e];
            *reinterpret_cast<float4*>(&C[(size_t)grow * N + gcol]) =
                *reinterpret_cast<const float4*>(out4a);
            *reinterpret_cast<float4*>(&C[(size_t)grow * N + gcol + 4]) =
                *reinterpret_cast<const float4*>(out4b);
            __syncwarp();
        }
    }
}

// ---------------------------------------------------------------------------
// Launch
// ---------------------------------------------------------------------------
extern "C" void kernel_launch(void* const* d_in, const int* in_sizes, int n_in,
                              void* d_out, int out_size) {
    const float* x      = (const float*)d_in[0];
    const int*   q      = (const int*)  d_in[1];
    const float* scales = (const float*)d_in[2];
    const float* bias   = (const float*)d_in[3];
    float*       out    = (float*)d_out;

    const int O = in_sizes[3];                 // 4096
    const int K = in_sizes[1] / O;             // NB*BS = 4096
    const int M = in_sizes[0] / K;             // 4096
    const int N = O;

    // 0) Convert activations f32 -> f16
    size_t nx = (size_t)M * K;
    convert_x_kernel<<<(unsigned)((nx / 8 + 255) / 256), 256>>>(x, nx);

    // 1) Dequantize weights -> g_w (f16)
    int chunks = O * (K >> 3);
    dequant_kernel<<<(chunks + 255) / 256, 256>>>(q, scales, O, K);

    // 2) GEMM with fused bias epilogue
    dim3 grid(N / BN, M / BM);
    gemm_wmma_kernel<<<grid, 256>>>(bias, out, M, N, K);
}

// round 4
// speedup vs baseline: 1.2334x; 1.2334x over previous
#include <cuda_runtime.h>
#include <cuda_fp16.h>
#include <cstdint>

// ---------------------------------------------------------------------------
// y[b,s,o] = sum_i x[b,s,i]*w[o,i] + bias[o],  w = (q-128)*scale (Q8_0)
// Harness dtypes (f16 promoted to f32): x f32 [4,1024,4096], q i32
// [4096,128,32], scales f32 [4096,128], bias f32 [4096] -> out f32.
// GEMM: A = x [M=4096,K=4096] f16, B = w [N=4096,K] f16 row-major (acts as
// col-major (k,n) for mma.sync.row.col), C [M,N] f32.
// NOTE: harness PTX target is compute_103 (no 'a') -> tcgen05 unavailable.
// Use mma.sync.m16n8k16 + ldmatrix + 3-stage cp.async pipeline instead.
// ---------------------------------------------------------------------------

#define MAX_O 4096
#define MAX_K 4096
#define MAX_M 4096

__device__ __half g_w[(size_t)MAX_O * MAX_K];  // dequantized weights [N,K]
__device__ __half g_x[(size_t)MAX_M * MAX_K];  // f16 activations    [M,K]

// ---------------------------------------------------------------------------
// Kernel 0: x f32 -> f16
// ---------------------------------------------------------------------------
__global__ void convert_x_kernel(const float* __restrict__ x, size_t n) {
    size_t i = ((size_t)blockIdx.x * blockDim.x + threadIdx.x) * 8;
    if (i >= n) return;
    const float4* xp = reinterpret_cast<const float4*>(x + i);
    float4 a = xp[0], b = xp[1];
    __half h[8];
    h[0] = __float2half(a.x); h[1] = __float2half(a.y);
    h[2] = __float2half(a.z); h[3] = __float2half(a.w);
    h[4] = __float2half(b.x); h[5] = __float2half(b.y);
    h[6] = __float2half(b.z); h[7] = __float2half(b.w);
    *reinterpret_cast<float4*>(&g_x[i]) = *reinterpret_cast<const float4*>(h);
}

// ---------------------------------------------------------------------------
// Kernel 1: q i32 -> f16 weights
// ---------------------------------------------------------------------------
__global__ void dequant_kernel(const int* __restrict__ q,
                               const float* __restrict__ scales,
                               int O, int K) {
    int c = blockIdx.x * blockDim.x + threadIdx.x;
    int chunks_per_row = K >> 3;
    if (c >= O * chunks_per_row) return;
    int o  = c / chunks_per_row;
    int k0 = (c - o * chunks_per_row) << 3;
    int nb = k0 >> 5;
    float s = scales[o * (K >> 5) + nb];

    const int4* qp = reinterpret_cast<const int4*>(q + (size_t)o * K + k0);
    int4 q0 = qp[0];
    int4 q1 = qp[1];

    __half h[8];
    h[0] = __float2half((float)(q0.x - 128) * s);
    h[1] = __float2half((float)(q0.y - 128) * s);
    h[2] = __float2half((float)(q0.z - 128) * s);
    h[3] = __float2half((float)(q0.w - 128) * s);
    h[4] = __float2half((float)(q1.x - 128) * s);
    h[5] = __float2half((float)(q1.y - 128) * s);
    h[6] = __float2half((float)(q1.z - 128) * s);
    h[7] = __float2half((float)(q1.w - 128) * s);

    *reinterpret_cast<float4*>(&g_w[(size_t)o * K + k0]) =
        *reinterpret_cast<const float4*>(h);
}

// ---------------------------------------------------------------------------
// GEMM: mma.sync m16n8k16, CTA 128x128x64, 8 warps (2x4), warp 64x32,
// 3-stage cp.async pipeline, SW128-swizzled smem, ldmatrix.x4.
// ---------------------------------------------------------------------------
constexpr int BM = 128, BN = 128, BK = 64;
constexpr int THREADS = 256;
constexpr int STAGES = 3;

constexpr int TILE_BYTES  = BM * 128;             // 16 KB (one of A or B)
constexpr int STAGE_BYTES = 2 * TILE_BYTES;       // 32 KB
constexpr int SM_BIAS = 0;                        // BN f32 = 512 B
constexpr int SM_TILES = 1024;                    // 1024-aligned
constexpr int SMEM_TOTAL = SM_TILES + STAGES * STAGE_BYTES;  // ~97.5 KB

__device__ __forceinline__ uint32_t smem_u32(const void* p) {
    uint32_t a;
    asm("{ .reg .u64 t; cvta.to.shared.u64 t, %1; cvt.u32.u64 %0, t; }"
        : "=r"(a) : "l"(p));
    return a;
}
__device__ __forceinline__ uint32_t sw128(uint32_t off) {
    return off ^ ((off >> 3) & 0x70);
}
__device__ __forceinline__ void cp16(uint32_t saddr, const void* gaddr) {
    asm volatile("cp.async.cg.shared.global [%0], [%1], 16;"
                 :: "r"(saddr), "l"(gaddr));
}
__device__ __forceinline__ void cp_commit() {
    asm volatile("cp.async.commit_group;" ::: "memory");
}
__device__ __forceinline__ void cp_wait1() {
    asm volatile("cp.async.wait_group 1;" ::: "memory");
}
__device__ __forceinline__ void ldmx4(uint32_t* r, uint32_t addr) {
    asm volatile("ldmatrix.sync.aligned.m8n8.x4.shared.b16 {%0,%1,%2,%3}, [%4];"
                 : "=r"(r[0]), "=r"(r[1]), "=r"(r[2]), "=r"(r[3]) : "r"(addr));
}
__device__ __forceinline__ void mma16816(float* c, const uint32_t* a,
                                         const uint32_t* b) {
    asm volatile(
        "mma.sync.aligned.m16n8k16.row.col.f32.f16.f16.f32 "
        "{%0,%1,%2,%3}, {%4,%5,%6,%7}, {%8,%9}, {%0,%1,%2,%3};"
        : "+f"(c[0]), "+f"(c[1]), "+f"(c[2]), "+f"(c[3])
        : "r"(a[0]), "r"(a[1]), "r"(a[2]), "r"(a[3]), "r"(b[0]), "r"(b[1]));
}

__global__ void __launch_bounds__(THREADS, 2)
gemm_mma_kernel(const float* __restrict__ bias,
                float* __restrict__ C, int M, int N, int K) {
    extern __shared__ char smem[];
    const uint32_t sb_tiles = smem_u32(smem + SM_TILES);
    const int tid  = threadIdx.x;
    const int wid  = tid >> 5;
    const int lane = tid & 31;
    const int bm = blockIdx.y * BM;
    const int bn = blockIdx.x * BN;

    const int wm_off = (wid >> 2) * 64;   // 0 or 64
    const int wn_off = (wid & 3) * 32;    // 0,32,64,96

    float* bias_s = (float*)(smem + SM_BIAS);
    if (tid < BN) bias_s[tid] = bias[bn + tid];

    const __half* Ag = g_x + (size_t)bm * K;
    const __half* Bg = g_w + (size_t)bn * K;

    // Per-thread load coords: 4 chunks of 16B for A, 4 for B, per stage.
    const int lr = tid >> 3;        // base row 0..31 (stride 32)
    const int lc = (tid & 7) * 8;   // half-offset within 64-wide row

    auto load_stage = [&](int stage, int kblk) {
        uint32_t a_s = sb_tiles + stage * STAGE_BYTES;
        uint32_t b_s = a_s + TILE_BYTES;
#pragma unroll
        for (int i = 0; i < 4; i++) {
            int r = lr + i * 32;
            cp16(a_s + sw128(r * 128 + lc * 2), Ag + (size_t)r * K + kblk + lc);
        }
#pragma unroll
        for (int i = 0; i < 4; i++) {
            int r = lr + i * 32;
            cp16(b_s + sw128(r * 128 + lc * 2), Bg + (size_t)r * K + kblk + lc);
        }
        cp_commit();
    };

    float acc[4][4][4];
#pragma unroll
    for (int mi = 0; mi < 4; mi++)
#pragma unroll
        for (int ni = 0; ni < 4; ni++)
#pragma unroll
            for (int e = 0; e < 4; e++) acc[mi][ni][e] = 0.0f;

    // Prologue: stages 0,1
    load_stage(0, 0);
    load_stage(1, BK);

    const int iters = K / BK;     // 64

    // ldmatrix lane addressing (byte offsets within tile, pre-swizzle):
    // A m16k16 frag: row = frag_m + (lane&15), chunk = lane>>4
    const int a_row_l = lane & 15;
    const int a_chk_l = lane >> 4;          // 0..1
    // B (x4 over n16): row = frag_n + (lane&7) + ((lane>>4)<<3), chunk=(lane>>3)&1
    const int b_row_l = (lane & 7) + ((lane >> 4) << 3);
    const int b_chk_l = (lane >> 3) & 1;

    for (int it = 0; it < iters; ++it) {
        cp_wait1();
        __syncthreads();

        if (it + STAGES - 1 < iters)
            load_stage((it + STAGES - 1) % STAGES, (it + STAGES - 1) * BK);
        else
            cp_commit();  // keep group counting aligned

        uint32_t a_s = sb_tiles + (it % STAGES) * STAGE_BYTES;
        uint32_t b_s = a_s + TILE_BYTES;

#pragma unroll
        for (int ks = 0; ks < BK / 16; ks++) {
            uint32_t afrag[4][4];
            uint32_t bfrag[2][4];
#pragma unroll
            for (int mi = 0; mi < 4; mi++) {
                int row = wm_off + mi * 16 + a_row_l;
                ldmx4(afrag[mi],
                      a_s + sw128(row * 128 + ks * 32 + a_chk_l * 16));
            }
#pragma unroll
            for (int nj = 0; nj < 2; nj++) {
                int row = wn_off + nj * 16 + b_row_l;
                ldmx4(bfrag[nj],
                      b_s + sw128(row * 128 + ks * 32 + b_chk_l * 16));
            }
#pragma unroll
            for (int mi = 0; mi < 4; mi++)
#pragma unroll
                for (int ni = 0; ni < 4; ni++)
                    mma16816(acc[mi][ni], afrag[mi], &bfrag[ni >> 1][(ni & 1) * 2]);
        }
    }

    // Epilogue: registers -> global, fused bias, float2 stores
#pragma unroll
    for (int mi = 0; mi < 4; mi++) {
        int r0 = bm + wm_off + mi * 16 + (lane >> 2);
#pragma unroll
        for (int ni = 0; ni < 4; ni++) {
            int col  = wn_off + ni * 8 + (lane & 3) * 2;
            float b0 = bias_s[col], b1 = bias_s[col + 1];
            float2 v0 = make_float2(acc[mi][ni][0] + b0, acc[mi][ni][1] + b1);
            float2 v1 = make_float2(acc[mi][ni][2] + b0, acc[mi][ni][3] + b1);
            *reinterpret_cast<float2*>(C + (size_t)r0 * N + bn + col) = v0;
            *reinterpret_cast<float2*>(C + (size_t)(r0 + 8) * N + bn + col) = v1;
        }
    }
}

// ---------------------------------------------------------------------------
// Launch
// ---------------------------------------------------------------------------
extern "C" void kernel_launch(void* const* d_in, const int* in_sizes, int n_in,
                              void* d_out, int out_size) {
    const float* x      = (const float*)d_in[0];
    const int*   q      = (const int*)  d_in[1];
    const float* scales = (const float*)d_in[2];
    const float* bias   = (const float*)d_in[3];
    float*       out    = (float*)d_out;

    const int O = in_sizes[3];                 // 4096
    const int K = in_sizes[1] / O;             // 4096
    const int M = in_sizes[0] / K;             // 4096
    const int N = O;

    size_t nx = (size_t)M * K;
    convert_x_kernel<<<(unsigned)((nx / 8 + 255) / 256), 256>>>(x, nx);

    int chunks = O * (K >> 3);
    dequant_kernel<<<(chunks + 255) / 256, 256>>>(q, scales, O, K);

    cudaFuncSetAttribute(gemm_mma_kernel,
                         cudaFuncAttributeMaxDynamicSharedMemorySize, SMEM_TOTAL);
    dim3 grid(N / BN, M / BM);
    gemm_mma_kernel<<<grid, THREADS, SMEM_TOTAL>>>(bias, out, M, N, K);
}